// round 6
// baseline (speedup 1.0000x reference)
#include <cuda_runtime.h>

// TrajectoryGeneratorAR_goal: S=256 rollouts x N=64 agents, OBS=8 encoder LSTM
// steps, PRED=12 autoregressive decoder steps with pairwise pooling net.
// One CTA per rollout, 256 threads, smem-resident.
// Round 6: pair-list sparsity (half the pooling work) combined with R1's
// proven ILP shape: 4 pairs per k-loop tile (4 independent pe/m register
// tiles), plain k-loop (no unroll pragma), natural occupancy (no reg cap —
// R5 showed forcing 128 regs spills and cancels the occupancy gain).

namespace {

constexpr int S_BATCH  = 256;
constexpr int NAG      = 64;
constexpr int BTOT     = S_BATCH * NAG;   // 16384
constexpr int OBS      = 8;
constexpr int PRED     = 12;
constexpr int H        = 16;
constexpr int NTHREADS = 256;
constexpr int MAXPAIRS = NAG * NAG;

struct __align__(16) Smem {
    float h[NAG][17];
    float c[NAG][17];
    float ctx[NAG][17];
    float hjp[NAG][65];
    float curr[NAG][2];
    float outp[NAG][2];
    float goal[NAG][2];
    unsigned long long nmask[NAG];
    int   pfx[NAG + 1];
    unsigned short plist[MAXPAIRS];    // (i<<6)|j, sorted by i
    alignas(16) float embW[32];
    alignas(16) float embB[16];
    alignas(16) float encWih[16*64];
    alignas(16) float encWhh[16*64];
    alignas(16) float encB[64];
    alignas(16) float decinW[18*16];
    alignas(16) float decinB[16];
    alignas(16) float decWih[16*64];
    alignas(16) float decWhh[16*64];
    alignas(16) float decB[64];
    alignas(16) float peW[32];
    alignas(16) float peB[16];
    alignas(16) float W1pT[64*16];   // [k][d]  (pool_W1 rows 0..15, transposed)
    alignas(16) float W1h [16*64];   // [d][k]  (pool_W1 rows 16..31)
    alignas(16) float b1  [64];
    alignas(16) float W2  [64*16];   // [k][u]
    alignas(16) float b2  [16];
    alignas(16) float h2p1W[18*16];
    alignas(16) float h2p1B[16];
    alignas(16) float h2p2W[16*4];
    alignas(16) float h2p2B[4];
};

__device__ __forceinline__ float sigm(float x)   { return 1.0f / (1.0f + __expf(-x)); }
__device__ __forceinline__ float tanh_f(float x) { return 2.0f / (1.0f + __expf(-2.0f * x)) - 1.0f; }

__device__ __forceinline__ void cpw(float* dst, const float* src, int n, int tid) {
    for (int k = tid; k < n; k += NTHREADS) dst[k] = src[k];
}

} // namespace

__global__ __launch_bounds__(NTHREADS)
void traj_ar_kernel(
    const float* __restrict__ traj_rel,
    const float* __restrict__ obs_pos,
    const float* __restrict__ goal_g,
    const float* __restrict__ embW, const float* __restrict__ embB,
    const float* __restrict__ encWih, const float* __restrict__ encWhh, const float* __restrict__ encB,
    const float* __restrict__ decinW, const float* __restrict__ decinB,
    const float* __restrict__ decWih, const float* __restrict__ decWhh, const float* __restrict__ decB,
    const float* __restrict__ peW, const float* __restrict__ peB,
    const float* __restrict__ W1, const float* __restrict__ b1,
    const float* __restrict__ W2, const float* __restrict__ b2,
    const float* __restrict__ h2p1W, const float* __restrict__ h2p1B,
    const float* __restrict__ h2p2W, const float* __restrict__ h2p2B,
    const int* __restrict__ nei,
    float* __restrict__ out, int out_size)
{
    extern __shared__ unsigned char smem_raw[];
    Smem& sm = *reinterpret_cast<Smem*>(smem_raw);
    const int tid = threadIdx.x;
    const int s   = blockIdx.x;

    if (s == 0 && tid == 0) {
        for (int idx = PRED * BTOT * 2; idx < out_size; ++idx) out[idx] = 0.0f;
    }

    // ---------------- weight staging + state init ----------------
    cpw(sm.embW,  embW,  32,  tid);  cpw(sm.embB,  embB,  16, tid);
    cpw(sm.encWih, encWih, 1024, tid); cpw(sm.encWhh, encWhh, 1024, tid); cpw(sm.encB, encB, 64, tid);
    cpw(sm.decinW, decinW, 288, tid);  cpw(sm.decinB, decinB, 16, tid);
    cpw(sm.decWih, decWih, 1024, tid); cpw(sm.decWhh, decWhh, 1024, tid); cpw(sm.decB, decB, 64, tid);
    cpw(sm.peW, peW, 32, tid); cpw(sm.peB, peB, 16, tid);
    for (int idx = tid; idx < 1024; idx += NTHREADS) {
        const int k = idx >> 4, d = idx & 15;
        sm.W1pT[idx] = W1[d * 64 + k];
    }
    cpw(sm.W1h, W1 + 1024, 1024, tid);
    cpw(sm.b1, b1, 64, tid); cpw(sm.W2, W2, 1024, tid); cpw(sm.b2, b2, 16, tid);
    cpw(sm.h2p1W, h2p1W, 288, tid); cpw(sm.h2p1B, h2p1B, 16, tid);
    cpw(sm.h2p2W, h2p2W, 64, tid);  cpw(sm.h2p2B, h2p2B, 4, tid);

    for (int idx = tid; idx < NAG * 17; idx += NTHREADS) {
        (&sm.h[0][0])[idx] = 0.0f; (&sm.c[0][0])[idx] = 0.0f; (&sm.ctx[0][0])[idx] = 0.0f;
    }
    if (tid < NAG) {
        sm.nmask[tid] = 0ull;
        const int b = s * NAG + tid;
        const float c0 = obs_pos[((OBS - 1) * BTOT + b) * 2 + 0];
        const float c1 = obs_pos[((OBS - 1) * BTOT + b) * 2 + 1];
        sm.curr[tid][0] = c0; sm.curr[tid][1] = c1;
        sm.outp[tid][0] = traj_rel[((OBS - 1) * BTOT + b) * 2 + 0];
        sm.outp[tid][1] = traj_rel[((OBS - 1) * BTOT + b) * 2 + 1];
        sm.goal[tid][0] = goal_g[b * 2 + 0] - c0;
        sm.goal[tid][1] = goal_g[b * 2 + 1] - c1;
    }
    __syncthreads();
    {
        const int base = s * (NAG * NAG);
        #pragma unroll
        for (int r = 0; r < (NAG * NAG) / NTHREADS; ++r) {
            const int flat = r * NTHREADS + tid;
            if (nei[base + flat] != 0)
                atomicOr(&sm.nmask[flat >> 6], 1ull << (flat & 63));
        }
    }
    __syncthreads();
    // ---- compacted (i,j) pair list, sorted by i (mask static over steps) ----
    if (tid == 0) {
        int run = 0;
        #pragma unroll
        for (int i = 0; i < NAG; ++i) { sm.pfx[i] = run; run += __popcll(sm.nmask[i]); }
        sm.pfx[NAG] = run;
    }
    __syncthreads();
    if (tid < NAG) {
        unsigned long long m = sm.nmask[tid];
        int w = sm.pfx[tid];
        const unsigned short ibase = (unsigned short)(tid << 6);
        while (m) {
            const int j = __ffsll((long long)m) - 1;
            m &= m - 1;
            sm.plist[w++] = (unsigned short)(ibase | j);
        }
    }
    __syncthreads();
    const int P       = sm.pfx[NAG];
    const int pbase   = P >> 8;
    const int prem    = P & (NTHREADS - 1);
    const int mystart = tid * pbase + (tid < prem ? tid : prem);
    const int mycnt   = pbase + (tid < prem ? 1 : 0);

    const int a   = tid >> 2;
    const int sub = tid & 3;

    // ---------------- history encoder ----------------
    for (int t = 0; t < OBS; ++t) {
        const int b = s * NAG + a;
        const float x0 = traj_rel[(t * BTOT + b) * 2 + 0];
        const float x1 = traj_rel[(t * BTOT + b) * 2 + 1];
        float emb[H];
        #pragma unroll
        for (int u = 0; u < H; ++u)
            emb[u] = fmaxf(fmaf(x0, sm.embW[u], fmaf(x1, sm.embW[16 + u], sm.embB[u])), 0.0f);
        float hold[H];
        #pragma unroll
        for (int d = 0; d < H; ++d) hold[d] = sm.h[a][d];
        float hn[4], cn[4];
        #pragma unroll
        for (int q = 0; q < 4; ++q) {
            const int u = sub * 4 + q;
            float gi = sm.encB[u], gf = sm.encB[16 + u], gg = sm.encB[32 + u], go = sm.encB[48 + u];
            #pragma unroll
            for (int d = 0; d < H; ++d) {
                const float e = emb[d], hd = hold[d];
                gi = fmaf(e, sm.encWih[d * 64 + u],        gi); gi = fmaf(hd, sm.encWhh[d * 64 + u],        gi);
                gf = fmaf(e, sm.encWih[d * 64 + 16 + u],   gf); gf = fmaf(hd, sm.encWhh[d * 64 + 16 + u],   gf);
                gg = fmaf(e, sm.encWih[d * 64 + 32 + u],   gg); gg = fmaf(hd, sm.encWhh[d * 64 + 32 + u],   gg);
                go = fmaf(e, sm.encWih[d * 64 + 48 + u],   go); go = fmaf(hd, sm.encWhh[d * 64 + 48 + u],   go);
            }
            const float cN = sigm(gf) * sm.c[a][u] + sigm(gi) * tanh_f(gg);
            cn[q] = cN; hn[q] = sigm(go) * tanh_f(cN);
        }
        __syncwarp();
        #pragma unroll
        for (int q = 0; q < 4; ++q) { sm.h[a][sub * 4 + q] = hn[q]; sm.c[a][sub * 4 + q] = cn[q]; }
        __syncwarp();
    }
    #pragma unroll
    for (int q = 0; q < 4; ++q) sm.c[a][sub * 4 + q] = 0.0f;
    __syncthreads();

    // ---------------- autoregressive decoder ----------------
    for (int step = 0; step < PRED; ++step) {
        // decoder input embed + LSTM (quad per agent)
        float ctxv[H];
        #pragma unroll
        for (int d = 0; d < H; ++d) ctxv[d] = sm.ctx[a][d];
        const float o0 = sm.outp[a][0], o1 = sm.outp[a][1];
        float emb[H];
        #pragma unroll
        for (int u = 0; u < H; ++u) {
            float acc = sm.decinB[u];
            #pragma unroll
            for (int d = 0; d < H; ++d) acc = fmaf(ctxv[d], sm.decinW[d * 16 + u], acc);
            acc = fmaf(o0, sm.decinW[256 + u], fmaf(o1, sm.decinW[272 + u], acc));
            emb[u] = fmaxf(acc, 0.0f);
        }
        float hold[H];
        #pragma unroll
        for (int d = 0; d < H; ++d) hold[d] = sm.h[a][d];
        float hn[4], cn[4];
        #pragma unroll
        for (int q = 0; q < 4; ++q) {
            const int u = sub * 4 + q;
            float gi = sm.decB[u], gf = sm.decB[16 + u], gg = sm.decB[32 + u], go = sm.decB[48 + u];
            #pragma unroll
            for (int d = 0; d < H; ++d) {
                const float e = emb[d], hd = hold[d];
                gi = fmaf(e, sm.decWih[d * 64 + u],        gi); gi = fmaf(hd, sm.decWhh[d * 64 + u],        gi);
                gf = fmaf(e, sm.decWih[d * 64 + 16 + u],   gf); gf = fmaf(hd, sm.decWhh[d * 64 + 16 + u],   gf);
                gg = fmaf(e, sm.decWih[d * 64 + 32 + u],   gg); gg = fmaf(hd, sm.decWhh[d * 64 + 32 + u],   gg);
                go = fmaf(e, sm.decWih[d * 64 + 48 + u],   go); go = fmaf(hd, sm.decWhh[d * 64 + 48 + u],   go);
            }
            const float cN = sigm(gf) * sm.c[a][u] + sigm(gi) * tanh_f(gg);
            cn[q] = cN; hn[q] = sigm(go) * tanh_f(cN);
        }
        __syncthreads();
        #pragma unroll
        for (int q = 0; q < 4; ++q) { sm.h[a][sub * 4 + q] = hn[q]; sm.c[a][sub * 4 + q] = cn[q]; }
        __syncthreads();

        // hjp[j][k] = h_j . W1h[:,k] + b1[k]; zero ctx accumulators
        {
            const int j = a, k0 = sub * 16;
            float hv[H];
            #pragma unroll
            for (int d = 0; d < H; ++d) hv[d] = sm.h[j][d];
            #pragma unroll
            for (int kk = 0; kk < 16; ++kk) {
                const int k = k0 + kk;
                float acc = sm.b1[k];
                #pragma unroll
                for (int d = 0; d < H; ++d) acc = fmaf(hv[d], sm.W1h[d * 64 + k], acc);
                sm.hjp[j][k] = acc;
            }
        }
        for (int idx = tid; idx < NAG * 17; idx += NTHREADS) (&sm.ctx[0][0])[idx] = 0.0f;
        __syncthreads();

        // ---- pooling over pair list: tiles of 4 pairs, R1-style ILP ----
        if (mycnt > 0) {
            int   cur_i = -1;
            float acc[H];
            for (int t = 0; t < mycnt; t += 4) {
                // fetch 4 pair slots, clamping to last real pair (pads get weight 0;
                // a pad duplicates the last pair's i so it never opens a new segment)
                int pi[4], pj[4];
                float pw[4];
                #pragma unroll
                for (int e = 0; e < 4; ++e) {
                    const int tt  = t + e;
                    const int idx = mystart + (tt < mycnt ? tt : mycnt - 1);
                    const int pr  = sm.plist[idx];
                    pi[e] = pr >> 6; pj[e] = pr & 63;
                    pw[e] = (tt < mycnt) ? 1.0f : 0.0f;
                }
                float pe[4][H], m[4][H];
                #pragma unroll
                for (int e = 0; e < 4; ++e) {
                    const float dx = sm.curr[pi[e]][0] - sm.curr[pj[e]][0];
                    const float dy = sm.curr[pi[e]][1] - sm.curr[pj[e]][1];
                    #pragma unroll
                    for (int u = 0; u < H; ++u) {
                        pe[e][u] = fmaxf(fmaf(dx, sm.peW[u], fmaf(dy, sm.peW[16 + u], sm.peB[u])), 0.0f);
                        m[e][u]  = 0.0f;
                    }
                }
                const float* __restrict__ hj0 = sm.hjp[pj[0]];
                const float* __restrict__ hj1 = sm.hjp[pj[1]];
                const float* __restrict__ hj2 = sm.hjp[pj[2]];
                const float* __restrict__ hj3 = sm.hjp[pj[3]];
                for (int k = 0; k < 64; ++k) {
                    const float4* w1p4 = reinterpret_cast<const float4*>(sm.W1pT + (k << 4));
                    const float4 wA = w1p4[0], wB = w1p4[1], wC = w1p4[2], wD = w1p4[3];
                    const float w1[H] = { wA.x, wA.y, wA.z, wA.w, wB.x, wB.y, wB.z, wB.w,
                                          wC.x, wC.y, wC.z, wC.w, wD.x, wD.y, wD.z, wD.w };
                    float a0 = hj0[k];
                    float a1 = hj1[k];
                    float a2 = hj2[k];
                    float a3 = hj3[k];
                    #pragma unroll
                    for (int d = 0; d < H; ++d) {
                        a0 = fmaf(pe[0][d], w1[d], a0);
                        a1 = fmaf(pe[1][d], w1[d], a1);
                        a2 = fmaf(pe[2][d], w1[d], a2);
                        a3 = fmaf(pe[3][d], w1[d], a3);
                    }
                    a0 = fmaxf(a0, 0.0f); a1 = fmaxf(a1, 0.0f);
                    a2 = fmaxf(a2, 0.0f); a3 = fmaxf(a3, 0.0f);
                    const float4* w2p4 = reinterpret_cast<const float4*>(sm.W2 + (k << 4));
                    const float4 vA = w2p4[0], vB = w2p4[1], vC = w2p4[2], vD = w2p4[3];
                    const float w2[H] = { vA.x, vA.y, vA.z, vA.w, vB.x, vB.y, vB.z, vB.w,
                                          vC.x, vC.y, vC.z, vC.w, vD.x, vD.y, vD.z, vD.w };
                    #pragma unroll
                    for (int u = 0; u < H; ++u) {
                        m[0][u] = fmaf(a0, w2[u], m[0][u]);
                        m[1][u] = fmaf(a1, w2[u], m[1][u]);
                        m[2][u] = fmaf(a2, w2[u], m[2][u]);
                        m[3][u] = fmaf(a3, w2[u], m[3][u]);
                    }
                }
                // epilogue: segment accumulation over i (list i-sorted)
                #pragma unroll
                for (int e = 0; e < 4; ++e) {
                    if (pi[e] == cur_i) {
                        #pragma unroll
                        for (int u = 0; u < H; ++u)
                            acc[u] = fmaf(pw[e], fmaxf(m[e][u] + sm.b2[u], 0.0f), acc[u]);
                    } else {
                        if (cur_i >= 0) {
                            #pragma unroll
                            for (int u = 0; u < H; ++u) atomicAdd(&sm.ctx[cur_i][u], acc[u]);
                        }
                        cur_i = pi[e];
                        #pragma unroll
                        for (int u = 0; u < H; ++u)
                            acc[u] = pw[e] * fmaxf(m[e][u] + sm.b2[u], 0.0f);
                    }
                }
            }
            if (cur_i >= 0) {
                #pragma unroll
                for (int u = 0; u < H; ++u) atomicAdd(&sm.ctx[cur_i][u], acc[u]);
            }
        }
        __syncthreads();

        // output head (one thread per agent)
        if (tid < NAG) {
            float hv[H], hh[H];
            #pragma unroll
            for (int u = 0; u < H; ++u) hv[u] = sm.h[tid][u] + sm.ctx[tid][u];
            const float g0 = sm.goal[tid][0], g1 = sm.goal[tid][1];
            #pragma unroll
            for (int u = 0; u < H; ++u) {
                float acc = sm.h2p1B[u];
                #pragma unroll
                for (int d = 0; d < H; ++d) acc = fmaf(hv[d], sm.h2p1W[d * 16 + u], acc);
                acc = fmaf(g0, sm.h2p1W[256 + u], fmaf(g1, sm.h2p1W[272 + u], acc));
                hh[u] = fmaxf(acc, 0.0f);
            }
            float mu0 = sm.h2p2B[0], mu1 = sm.h2p2B[1];
            #pragma unroll
            for (int d = 0; d < H; ++d) {
                mu0 = fmaf(hh[d], sm.h2p2W[d * 4 + 0], mu0);
                mu1 = fmaf(hh[d], sm.h2p2W[d * 4 + 1], mu1);
            }
            const int b = s * NAG + tid;
            out[(step * BTOT + b) * 2 + 0] = mu0;
            out[(step * BTOT + b) * 2 + 1] = mu1;
            sm.outp[tid][0] = mu0; sm.outp[tid][1] = mu1;
            sm.curr[tid][0] += mu0; sm.curr[tid][1] += mu1;
        }
        __syncthreads();
    }
}

extern "C" void kernel_launch(void* const* d_in, const int* in_sizes, int n_in,
                              void* d_out, int out_size)
{
    (void)in_sizes; (void)n_in;
    cudaFuncSetAttribute(traj_ar_kernel, cudaFuncAttributeMaxDynamicSharedMemorySize,
                         (int)sizeof(Smem));
    traj_ar_kernel<<<S_BATCH, NTHREADS, sizeof(Smem)>>>(
        (const float*)d_in[0],
        (const float*)d_in[1],
        (const float*)d_in[2],
        (const float*)d_in[4],  (const float*)d_in[5],
        (const float*)d_in[6],  (const float*)d_in[7],  (const float*)d_in[8],
        (const float*)d_in[9],  (const float*)d_in[10],
        (const float*)d_in[11], (const float*)d_in[12], (const float*)d_in[13],
        (const float*)d_in[14], (const float*)d_in[15],
        (const float*)d_in[16], (const float*)d_in[17],
        (const float*)d_in[18], (const float*)d_in[19],
        (const float*)d_in[20], (const float*)d_in[21],
        (const float*)d_in[22], (const float*)d_in[23],
        (const int*)d_in[24],
        (float*)d_out, out_size);
}